// round 1
// baseline (speedup 1.0000x reference)
#include <cuda_runtime.h>
#include <cstdint>

#define HID     64
#define SLEN    24
#define VOC     64
#define ITEMS   256
#define THREADS 512
#define ZSTRIDE 65

// Precomputed tables (device globals; no allocation).
__device__ float g_pre1[VOC * HID];   // pre1[t][o] = embed[t] . W1[o][0:64]  + b1[o]
__device__ float g_pre2[VOC * HID];   // pre2[t][o] = 0.125 * embed[t] . W1[o][64:128]
__device__ float g_w2t [HID * HID];   // w2t[j][o]  = W2[o][j]

__global__ void precompute_kernel(const float* __restrict__ embed_W,
                                  const float* __restrict__ W1,
                                  const float* __restrict__ b1,
                                  const float* __restrict__ W2)
{
    int gid = blockIdx.x * blockDim.x + threadIdx.x;
    if (gid >= VOC * HID) return;
    int t = gid >> 6;        // token (or j for w2t)
    int o = gid & 63;        // output dim
    const float* e   = embed_W + t * HID;
    const float* w1o = W1 + o * (2 * HID);
    float s1 = 0.f, s2 = 0.f;
#pragma unroll 16
    for (int k = 0; k < HID; k++) {
        float ek = e[k];
        s1 = fmaf(ek, w1o[k],        s1);
        s2 = fmaf(ek, w1o[HID + k],  s2);
    }
    g_pre1[gid] = s1 + b1[o];
    g_pre2[gid] = s2 * 0.125f;
    g_w2t [gid] = W2[o * HID + t];   // t plays the role of j here
}

// smem layout (floats):
//  [0,4096)      s_pre1
//  [4096,8192)   s_pre2
//  [8192,12288)  s_w2t
//  [12288,12352) s_b2
//  [12352, +256*65) s_z   (h rows, stride 65 -> conflict-free per-thread reads)
#define SM_FLOATS (12352 + ITEMS * ZSTRIDE)
#define SM_BYTES  (SM_FLOATS * 4)

__global__ __launch_bounds__(THREADS, 1)
void lru_main(const int*  __restrict__ seqs,
              const int*  __restrict__ query_tok,
              const float* __restrict__ b2,
              float* __restrict__ out,
              int B)
{
    extern __shared__ float sm[];
    float* s_pre1 = sm;
    float* s_pre2 = sm + 4096;
    float* s_wt   = sm + 8192;
    float* s_b2   = sm + 12288;
    float* s_z    = sm + 12352;
    const int tid  = threadIdx.x;
    const int warp = tid >> 5;
    const int lane = tid & 31;
    const int blockBase = blockIdx.x * ITEMS;

    // ---- load tables into smem (float4, coalesced) ----
    {
        float4*       d  = (float4*)sm;
        const float4* s1 = (const float4*)g_pre1;
        const float4* s2 = (const float4*)g_pre2;
        const float4* s3 = (const float4*)g_w2t;
#pragma unroll
        for (int i = tid; i < 1024; i += THREADS) d[i]        = s1[i];
#pragma unroll
        for (int i = tid; i < 1024; i += THREADS) d[1024 + i] = s2[i];
#pragma unroll
        for (int i = tid; i < 1024; i += THREADS) d[2048 + i] = s3[i];
        if (tid < 16) ((float4*)s_b2)[tid] = ((const float4*)b2)[tid];
    }

    // ---- phase A: indices. 16 warps x 16 items; lanes 0..15 own one item each.
    // Pack 9 six-bit tokens into two u32 so the gather loop needs only 2 shuffles/item.
    unsigned pa = 0, pb = 0;
    {
        int it = blockBase + warp * 16 + lane;
        if (lane < 16 && it < B) {
            const int* row = seqs + it * SLEN;          // row is 16B-aligned (96B stride)
            int  t0  = row[15];
            int4 t14 = *(const int4*)(row + 16);        // tokens 16..19
            int2 t56 = *(const int2*)(row + 20);        // tokens 20..21
            int  t7  = row[22];
            int  tq  = query_tok[it];
            pa = (unsigned)t0 | ((unsigned)t14.x << 6) | ((unsigned)t14.y << 12)
               | ((unsigned)t14.z << 18) | ((unsigned)t14.w << 24);
            pb = (unsigned)t56.x | ((unsigned)t56.y << 6) | ((unsigned)t7 << 12)
               | ((unsigned)tq << 18);
        }
    }
    __syncthreads();   // tables visible

    // ---- phase A: gather z = pre1[q] + sum pre2[mem_j], relu, stage into s_z.
    // Warp-per-item: lanes read consecutive float2 of one table row -> conflict-free.
#pragma unroll 2
    for (int m = 0; m < 16; m++) {
        unsigned am = __shfl_sync(0xffffffffu, pa, m);
        unsigned bm = __shfl_sync(0xffffffffu, pb, m);
        int q = (bm >> 18) & 63;
        float2 z = ((const float2*)(s_pre1 + q * HID))[lane];
#pragma unroll
        for (int s = 0; s < 5; s++) {
            int tk = (am >> (6 * s)) & 63;
            float2 v = ((const float2*)(s_pre2 + tk * HID))[lane];
            z.x += v.x; z.y += v.y;
        }
#pragma unroll
        for (int s = 0; s < 3; s++) {
            int tk = (bm >> (6 * s)) & 63;
            float2 v = ((const float2*)(s_pre2 + tk * HID))[lane];
            z.x += v.x; z.y += v.y;
        }
        float* zr = s_z + (warp * 16 + m) * ZSTRIDE + 2 * lane;
        zr[0] = fmaxf(z.x, 0.f);
        zr[1] = fmaxf(z.y, 0.f);
    }
    __syncthreads();

    // ---- phase B: logits = h @ W2^T + b2, packed f32x2 FMAs.
    // 2 threads per item: thread (i, half) computes outputs [half*32, half*32+32).
    const int i    = tid & 255;
    const int half = tid >> 8;
    const float* zrow = s_z + i * ZSTRIDE;

    unsigned long long acc[16];
    {
        const unsigned long long* bb = (const unsigned long long*)(s_b2 + half * 32);
#pragma unroll
        for (int p = 0; p < 16; p++) acc[p] = bb[p];
    }
    const float* wbase_f = s_wt + half * 32;
#pragma unroll 2
    for (int j = 0; j < 64; j++) {
        float hj = zrow[j];                       // bank (i+j)%32 -> conflict-free
        unsigned long long hd;
        asm("mov.b64 %0, {%1, %1};" : "=l"(hd) : "f"(hj));
        const ulonglong2* wr = (const ulonglong2*)(wbase_f + j * 64);  // broadcast LDS.128
#pragma unroll
        for (int p2 = 0; p2 < 8; p2++) {
            ulonglong2 w = wr[p2];
            asm("fma.rn.f32x2 %0, %1, %2, %0;" : "+l"(acc[2 * p2])     : "l"(w.x), "l"(hd));
            asm("fma.rn.f32x2 %0, %1, %2, %0;" : "+l"(acc[2 * p2 + 1]) : "l"(w.y), "l"(hd));
        }
    }
    __syncthreads();   // everyone done READING s_z before we overwrite it

    // stage outputs back into s_z (own row region; scalar STS, conflict-free pattern)
    {
        float* zw = s_z + i * ZSTRIDE + half * 32;
#pragma unroll
        for (int p = 0; p < 16; p++) {
            float lo, hi;
            asm("mov.b64 {%0, %1}, %2;" : "=f"(lo), "=f"(hi) : "l"(acc[p]));
            zw[2 * p]     = lo;
            zw[2 * p + 1] = hi;
        }
    }
    __syncthreads();

    // ---- coalesced copy-out: 4096 float4 per block, STG.128 fully coalesced.
    {
        float4* o4 = (float4*)(out + (size_t)blockBase * HID);
#pragma unroll
        for (int v = tid; v < ITEMS * 16; v += THREADS) {
            int ii = v >> 4, c = v & 15;
            if (blockBase + ii < B) {
                const float* zr = s_z + ii * ZSTRIDE + c * 4;
                o4[v] = make_float4(zr[0], zr[1], zr[2], zr[3]);
            }
        }
    }
}

extern "C" void kernel_launch(void* const* d_in, const int* in_sizes, int n_in,
                              void* d_out, int out_size)
{
    const int*   seqs   = (const int*)  d_in[0];
    const int*   query  = (const int*)  d_in[1];
    const float* embedW = (const float*)d_in[2];
    const float* W1     = (const float*)d_in[3];
    const float* b1     = (const float*)d_in[4];
    const float* W2     = (const float*)d_in[5];
    const float* b2     = (const float*)d_in[6];
    float*       out    = (float*)d_out;

    const int B = in_sizes[0] / SLEN;

    precompute_kernel<<<(VOC * HID + 255) / 256, 256>>>(embedW, W1, b1, W2);

    cudaFuncSetAttribute(lru_main, cudaFuncAttributeMaxDynamicSharedMemorySize, SM_BYTES);
    const int grid = (B + ITEMS - 1) / ITEMS;
    lru_main<<<grid, THREADS, SM_BYTES>>>(seqs, query, b2, out, B);
}

// round 4
// speedup vs baseline: 2.6197x; 2.6197x over previous
#include <cuda_runtime.h>
#include <cuda_fp16.h>
#include <cstdint>

#define HID     64
#define SLEN    24
#define ITEMS   128
#define THREADS 256

// Precomputed tables (device globals; no allocation).
__device__ float    g_pre1[4096];   // pre1[t][o] = embed[t].W1[o][0:64] + b1[o]
__device__ float    g_pre2[4096];   // pre2[t][o] = 0.125 * embed[t].W1[o][64:128]
__device__ unsigned g_w2h [2048];   // W2 as fp16x2 pairs, row-major [n=64][k=64]

// ---------------------------------------------------------------------------
// Precompute: one warp per (t,o) output; lanes split K=64, shfl-reduce.
// First 2048 flat threads also convert W2 -> fp16x2.
// ---------------------------------------------------------------------------
__global__ void precompute_kernel(const float* __restrict__ embed_W,
                                  const float* __restrict__ W1,
                                  const float* __restrict__ b1,
                                  const float* __restrict__ W2)
{
    int warpId = (blockIdx.x * blockDim.x + threadIdx.x) >> 5;   // 0..4095
    int lane   = threadIdx.x & 31;
    int t = warpId >> 6;
    int o = warpId & 63;
    const float* e   = embed_W + t * HID;
    const float* w1o = W1 + o * (2 * HID);
    float e1 = e[lane], e2 = e[lane + 32];
    float s1 = e1 * w1o[lane]      + e2 * w1o[lane + 32];
    float s2 = e1 * w1o[64 + lane] + e2 * w1o[96 + lane];
#pragma unroll
    for (int d = 16; d > 0; d >>= 1) {
        s1 += __shfl_xor_sync(0xffffffffu, s1, d);
        s2 += __shfl_xor_sync(0xffffffffu, s2, d);
    }
    if (lane == 0) {
        g_pre1[warpId] = s1 + b1[o];
        g_pre2[warpId] = s2 * 0.125f;
    }
    int flat = blockIdx.x * blockDim.x + threadIdx.x;
    if (flat < 2048) {
        int n = flat >> 5, kk = flat & 31;
        __half2 h2 = __floats2half2_rn(W2[n * 64 + 2 * kk], W2[n * 64 + 2 * kk + 1]);
        g_w2h[flat] = *(unsigned*)&h2;
    }
}

// ---------------------------------------------------------------------------
// Main kernel. smem layout (bytes):
//   [0,16384)        s_pre1  fp32 [64][64]
//   [16384,32768)    s_pre2  fp32 [64][64]
//   [32768,41984)    s_w2    fp16 [64 rows][72]  (144B padded rows)
//   [41984,60416)    s_H     fp16 [128 rows][72] (144B padded rows)
//   [60416,60672)    s_b2    fp32 [64]
// ---------------------------------------------------------------------------
#define OFF_PRE1   0
#define OFF_PRE2   16384
#define OFF_W2H    32768
#define OFF_H      41984
#define OFF_B2     60416
#define SMEM_TOTAL 60672
#define ROWB       144          // padded row stride in bytes

__global__ __launch_bounds__(THREADS, 2)
void lru_main(const int*   __restrict__ seqs,
              const int*   __restrict__ query_tok,
              const float* __restrict__ b2,
              float*       __restrict__ out,
              int B)
{
    extern __shared__ char sm[];
    float* s_pre1 = (float*)(sm + OFF_PRE1);
    float* s_pre2 = (float*)(sm + OFF_PRE2);
    char*  s_w2   = sm + OFF_W2H;
    char*  s_H    = sm + OFF_H;
    float* s_b2   = (float*)(sm + OFF_B2);

    const int tid  = threadIdx.x;
    const int warp = tid >> 5;
    const int lane = tid & 31;
    const int blockBase = blockIdx.x * ITEMS;

    // ---- load tables into smem ----
    {
        const float4* s1 = (const float4*)g_pre1;
        const float4* s2 = (const float4*)g_pre2;
        float4* d1 = (float4*)s_pre1;
        float4* d2 = (float4*)s_pre2;
#pragma unroll
        for (int i = tid; i < 1024; i += THREADS) d1[i] = s1[i];
#pragma unroll
        for (int i = tid; i < 1024; i += THREADS) d2[i] = s2[i];
#pragma unroll
        for (int i = tid; i < 2048; i += THREADS) {
            int n = i >> 5, kk = i & 31;
            *(unsigned*)(s_w2 + n * ROWB + kk * 4) = g_w2h[i];
        }
        if (tid < 16) ((float4*)s_b2)[tid] = ((const float4*)b2)[tid];
    }
    __syncthreads();

    // ---- gather: warp w owns items [16w, 16w+16) == its own M-tile rows ----
    unsigned pa = 0, pb = 0;
    {
        int it = blockBase + warp * 16 + lane;
        if (lane < 16 && it < B) {
            const int* row = seqs + (size_t)it * SLEN;   // 96B stride: row+16 is 16B aligned
            int  t0  = row[15];
            int4 t14 = *(const int4*)(row + 16);
            int2 t56 = *(const int2*)(row + 20);
            int  t7  = row[22];
            int  tq  = query_tok[it];
            pa = (unsigned)t0 | ((unsigned)t14.x << 6) | ((unsigned)t14.y << 12)
               | ((unsigned)t14.z << 18) | ((unsigned)t14.w << 24);
            pb = (unsigned)t56.x | ((unsigned)t56.y << 6) | ((unsigned)t7 << 12)
               | ((unsigned)tq << 18);
        }
    }
#pragma unroll 2
    for (int m = 0; m < 16; m++) {
        unsigned am = __shfl_sync(0xffffffffu, pa, m);
        unsigned bm = __shfl_sync(0xffffffffu, pb, m);
        int q = (bm >> 18) & 63;
        float2 z = ((const float2*)(s_pre1 + q * HID))[lane];
#pragma unroll
        for (int s = 0; s < 5; s++) {
            int tk = (am >> (6 * s)) & 63;
            float2 v = ((const float2*)(s_pre2 + tk * HID))[lane];
            z.x += v.x; z.y += v.y;
        }
#pragma unroll
        for (int s = 0; s < 3; s++) {
            int tk = (bm >> (6 * s)) & 63;
            float2 v = ((const float2*)(s_pre2 + tk * HID))[lane];
            z.x += v.x; z.y += v.y;
        }
        z.x = fmaxf(z.x, 0.f);
        z.y = fmaxf(z.y, 0.f);
        unsigned packed;                       // lo = z.x (col 2*lane), hi = z.y
        asm("cvt.rn.f16x2.f32 %0, %1, %2;" : "=r"(packed) : "f"(z.y), "f"(z.x));
        // row = warp*16+m, cols [2*lane, 2*lane+1]; bank (36r+lane)%32 conflict-free
        *(unsigned*)(s_H + (warp * 16 + m) * ROWB + lane * 4) = packed;
    }
    __syncwarp();   // warp's own H rows visible to all its lanes

    // ---- MMA: warp computes rows [16w,16w+16) x all 64 cols via 8n x 4k HMMA ----
    const int r = lane >> 2;        // 0..7
    const int c = lane & 3;         // 0..3
    float acc[8][4];
#pragma unroll
    for (int nt = 0; nt < 8; nt++) {
        int col = 8 * nt + 2 * c;
        acc[nt][0] = s_b2[col];
        acc[nt][1] = s_b2[col + 1];
        acc[nt][2] = acc[nt][0];
        acc[nt][3] = acc[nt][1];
    }
    const char* Ab = s_H + (warp * 16 + r) * ROWB + 4 * c;
#pragma unroll
    for (int kt = 0; kt < 4; kt++) {
        unsigned a0 = *(const unsigned*)(Ab + 32 * kt);              // row r,   k0
        unsigned a1 = *(const unsigned*)(Ab + 8 * ROWB + 32 * kt);   // row r+8, k0
        unsigned a2 = *(const unsigned*)(Ab + 16 + 32 * kt);         // row r,   k0+8
        unsigned a3 = *(const unsigned*)(Ab + 8 * ROWB + 16 + 32 * kt);
#pragma unroll
        for (int nt = 0; nt < 8; nt++) {
            const char* Bb = s_w2 + (8 * nt + r) * ROWB + 4 * c + 32 * kt;
            unsigned b0 = *(const unsigned*)(Bb);        // n, k0..k0+1
            unsigned b1 = *(const unsigned*)(Bb + 16);   // n, k0+8..k0+9
            asm volatile(
                "mma.sync.aligned.m16n8k16.row.col.f32.f16.f16.f32 "
                "{%0,%1,%2,%3}, {%4,%5,%6,%7}, {%8,%9}, {%0,%1,%2,%3};"
                : "+f"(acc[nt][0]), "+f"(acc[nt][1]), "+f"(acc[nt][2]), "+f"(acc[nt][3])
                : "r"(a0), "r"(a1), "r"(a2), "r"(a3), "r"(b0), "r"(b1));
        }
    }

    // ---- epilogue: direct float2 stores (L2 merges into full lines) ----
    {
        int item0 = blockBase + warp * 16 + r;
        int item1 = item0 + 8;
        float* o0 = out + (size_t)item0 * HID + 2 * c;
        float* o1 = out + (size_t)item1 * HID + 2 * c;
        if (item1 < B) {
#pragma unroll
            for (int nt = 0; nt < 8; nt++) {
                *(float2*)(o0 + 8 * nt) = make_float2(acc[nt][0], acc[nt][1]);
                *(float2*)(o1 + 8 * nt) = make_float2(acc[nt][2], acc[nt][3]);
            }
        } else {
#pragma unroll
            for (int nt = 0; nt < 8; nt++) {
                if (item0 < B) *(float2*)(o0 + 8 * nt) = make_float2(acc[nt][0], acc[nt][1]);
                if (item1 < B) *(float2*)(o1 + 8 * nt) = make_float2(acc[nt][2], acc[nt][3]);
            }
        }
    }
}

extern "C" void kernel_launch(void* const* d_in, const int* in_sizes, int n_in,
                              void* d_out, int out_size)
{
    const int*   seqs   = (const int*)  d_in[0];
    const int*   query  = (const int*)  d_in[1];
    const float* embedW = (const float*)d_in[2];
    const float* W1     = (const float*)d_in[3];
    const float* b1     = (const float*)d_in[4];
    const float* W2     = (const float*)d_in[5];
    const float* b2     = (const float*)d_in[6];
    float*       out    = (float*)d_out;

    const int B = in_sizes[0] / SLEN;

    precompute_kernel<<<512, 256>>>(embedW, W1, b1, W2);

    cudaFuncSetAttribute(lru_main, cudaFuncAttributeMaxDynamicSharedMemorySize, SMEM_TOTAL);
    const int grid = (B + ITEMS - 1) / ITEMS;
    lru_main<<<grid, THREADS, SMEM_TOTAL>>>(seqs, query, b2, out, B);
}

// round 6
// speedup vs baseline: 3.0239x; 1.1543x over previous
#include <cuda_runtime.h>
#include <cuda_fp16.h>
#include <cstdint>

#define HID     64
#define SLEN    24
#define ITEMS   128
#define THREADS 256

// Precomputed tables (device globals; no allocation).
__device__ float    g_pre1[4096];   // pre1[t][o] = embed[t].W1[o][0:64] + b1[o]
__device__ float    g_pre2[4096];   // pre2[t][o] = 0.125 * embed[t].W1[o][64:128]
__device__ unsigned g_w2h [2048];   // W2 as fp16x2 pairs, row-major [n=64][k=64]

// ---------------------------------------------------------------------------
// Precompute: one warp per (t,o) output; lanes split K=64, shfl-reduce.
// First 2048 flat threads also convert W2 -> fp16x2.
// ---------------------------------------------------------------------------
__global__ void precompute_kernel(const float* __restrict__ embed_W,
                                  const float* __restrict__ W1,
                                  const float* __restrict__ b1,
                                  const float* __restrict__ W2)
{
    int warpId = (blockIdx.x * blockDim.x + threadIdx.x) >> 5;   // 0..4095
    int lane   = threadIdx.x & 31;
    int t = warpId >> 6;
    int o = warpId & 63;
    const float* e   = embed_W + t * HID;
    const float* w1o = W1 + o * (2 * HID);
    float e1 = e[lane], e2 = e[lane + 32];
    float s1 = e1 * w1o[lane]      + e2 * w1o[lane + 32];
    float s2 = e1 * w1o[64 + lane] + e2 * w1o[96 + lane];
#pragma unroll
    for (int d = 16; d > 0; d >>= 1) {
        s1 += __shfl_xor_sync(0xffffffffu, s1, d);
        s2 += __shfl_xor_sync(0xffffffffu, s2, d);
    }
    if (lane == 0) {
        g_pre1[warpId] = s1 + b1[o];
        g_pre2[warpId] = s2 * 0.125f;
    }
    int flat = blockIdx.x * blockDim.x + threadIdx.x;
    if (flat < 2048) {
        int n = flat >> 5, kk = flat & 31;
        __half2 h2 = __floats2half2_rn(W2[n * 64 + 2 * kk], W2[n * 64 + 2 * kk + 1]);
        g_w2h[flat] = *(unsigned*)&h2;
    }
}

// ---------------------------------------------------------------------------
// Main kernel. smem layout (bytes):
//   [0,16384)        s_pre1  fp32 [64][64]
//   [16384,24576)    s_pre2h fp16 [64][64]            (128B rows)
//   [24576,33792)    s_w2    fp16 [64 rows][72]       (144B padded rows)
//   [33792,52224)    s_H     fp16 [128 rows][72]      (144B padded rows)
//   [52224,52480)    s_b2    fp32 [64]
// ---------------------------------------------------------------------------
#define OFF_PRE1   0
#define OFF_PRE2H  16384
#define OFF_W2H    24576
#define OFF_H      33792
#define OFF_B2     52224
#define SMEM_TOTAL 52480
#define ROWB       144          // padded row stride in bytes

__global__ __launch_bounds__(THREADS, 3)
void lru_main(const int*   __restrict__ seqs,
              const int*   __restrict__ query_tok,
              const float* __restrict__ b2,
              float*       __restrict__ out,
              int B)
{
    extern __shared__ char sm[];
    float*    s_pre1  = (float*)(sm + OFF_PRE1);
    unsigned* s_pre2h = (unsigned*)(sm + OFF_PRE2H);
    char*     s_w2    = sm + OFF_W2H;
    char*     s_H     = sm + OFF_H;
    float*    s_b2    = (float*)(sm + OFF_B2);

    const int tid  = threadIdx.x;
    const int warp = tid >> 5;
    const int lane = tid & 31;
    const int blockBase = blockIdx.x * ITEMS;

    // ---- index loads first (overlap GMEM latency with table staging) ----
    unsigned pa = 0, pb = 0;
    {
        int it = blockBase + warp * 16 + lane;
        if (lane < 16 && it < B) {
            const int* row = seqs + (size_t)it * SLEN;   // 96B stride: row+16 is 16B aligned
            int  t0  = row[15];
            int4 t14 = *(const int4*)(row + 16);
            int2 t56 = *(const int2*)(row + 20);
            int  t7  = row[22];
            int  tq  = query_tok[it];
            pa = (unsigned)t0 | ((unsigned)t14.x << 6) | ((unsigned)t14.y << 12)
               | ((unsigned)t14.z << 18) | ((unsigned)t14.w << 24);
            pb = (unsigned)t56.x | ((unsigned)t56.y << 6) | ((unsigned)t7 << 12)
               | ((unsigned)tq << 18);
        }
    }

    // ---- stage tables into smem ----
    {
        const float4* s1 = (const float4*)g_pre1;
        const float4* s2 = (const float4*)g_pre2;
        float4* d1 = (float4*)s_pre1;
#pragma unroll
        for (int i = tid; i < 1024; i += THREADS) d1[i] = s1[i];
#pragma unroll
        for (int i = tid; i < 1024; i += THREADS) {       // fp32 -> fp16 on the fly
            float4 v = s2[i];
            __half2 lo = __floats2half2_rn(v.x, v.y);
            __half2 hi = __floats2half2_rn(v.z, v.w);
            ((uint2*)s_pre2h)[i] = make_uint2(*(unsigned*)&lo, *(unsigned*)&hi);
        }
#pragma unroll
        for (int i = tid; i < 2048; i += THREADS) {
            int n = i >> 5, kk = i & 31;
            *(unsigned*)(s_w2 + n * ROWB + kk * 4) = g_w2h[i];
        }
        if (tid < 16) ((float4*)s_b2)[tid] = ((const float4*)b2)[tid];
    }
    __syncthreads();

    // ---- gather: warp w owns items [16w, 16w+16) == its own M-tile rows ----
    // pre1 row: fp32 (exact, large term). pre2 rows: fp16 loads, fp32 accumulate.
#pragma unroll 2
    for (int m = 0; m < 16; m++) {
        unsigned am = __shfl_sync(0xffffffffu, pa, m);
        unsigned bm = __shfl_sync(0xffffffffu, pb, m);
        int q = (bm >> 18) & 63;
        float2 z = ((const float2*)(s_pre1 + q * HID))[lane];
#pragma unroll
        for (int s = 0; s < 5; s++) {
            int tk = (am >> (6 * s)) & 63;
            unsigned u = s_pre2h[tk * 32 + lane];
            float2 v = __half22float2(*(const __half2*)&u);
            z.x += v.x; z.y += v.y;
        }
#pragma unroll
        for (int s = 0; s < 3; s++) {
            int tk = (bm >> (6 * s)) & 63;
            unsigned u = s_pre2h[tk * 32 + lane];
            float2 v = __half22float2(*(const __half2*)&u);
            z.x += v.x; z.y += v.y;
        }
        z.x = fmaxf(z.x, 0.f);
        z.y = fmaxf(z.y, 0.f);
        unsigned packed;                       // lo = z.x (col 2*lane), hi = z.y
        asm("cvt.rn.f16x2.f32 %0, %1, %2;" : "=r"(packed) : "f"(z.y), "f"(z.x));
        // row = warp*16+m, cols [2*lane, 2*lane+1]; bank (36r+lane)%32 conflict-free
        *(unsigned*)(s_H + (warp * 16 + m) * ROWB + lane * 4) = packed;
    }
    __syncwarp();   // warp's own H rows visible to all its lanes

    // ---- MMA: warp computes rows [16w,16w+16) x all 64 cols via 8n x 4k HMMA ----
    const int r = lane >> 2;        // 0..7
    const int c = lane & 3;         // 0..3
    float acc[8][4];
#pragma unroll
    for (int nt = 0; nt < 8; nt++) {
        int col = 8 * nt + 2 * c;
        acc[nt][0] = s_b2[col];
        acc[nt][1] = s_b2[col + 1];
        acc[nt][2] = acc[nt][0];
        acc[nt][3] = acc[nt][1];
    }
    const char* Ab = s_H + (warp * 16 + r) * ROWB + 4 * c;
#pragma unroll
    for (int kt = 0; kt < 4; kt++) {
        unsigned a0 = *(const unsigned*)(Ab + 32 * kt);              // row r,   k0
        unsigned a1 = *(const unsigned*)(Ab + 8 * ROWB + 32 * kt);   // row r+8, k0
        unsigned a2 = *(const unsigned*)(Ab + 16 + 32 * kt);         // row r,   k0+8
        unsigned a3 = *(const unsigned*)(Ab + 8 * ROWB + 16 + 32 * kt);
#pragma unroll
        for (int nt = 0; nt < 8; nt++) {
            const char* Bb = s_w2 + (8 * nt + r) * ROWB + 4 * c + 32 * kt;
            unsigned b0 = *(const unsigned*)(Bb);        // n, k0..k0+1
            unsigned b1 = *(const unsigned*)(Bb + 16);   // n, k0+8..k0+9
            asm volatile(
                "mma.sync.aligned.m16n8k16.row.col.f32.f16.f16.f32 "
                "{%0,%1,%2,%3}, {%4,%5,%6,%7}, {%8,%9}, {%0,%1,%2,%3};"
                : "+f"(acc[nt][0]), "+f"(acc[nt][1]), "+f"(acc[nt][2]), "+f"(acc[nt][3])
                : "r"(a0), "r"(a1), "r"(a2), "r"(a3), "r"(b0), "r"(b1));
        }
    }

    // ---- epilogue: direct float2 stores (L2 merges into full lines) ----
    {
        int item0 = blockBase + warp * 16 + r;
        int item1 = item0 + 8;
        float* o0 = out + (size_t)item0 * HID + 2 * c;
        float* o1 = out + (size_t)item1 * HID + 2 * c;
        if (item1 < B) {
#pragma unroll
            for (int nt = 0; nt < 8; nt++) {
                *(float2*)(o0 + 8 * nt) = make_float2(acc[nt][0], acc[nt][1]);
                *(float2*)(o1 + 8 * nt) = make_float2(acc[nt][2], acc[nt][3]);
            }
        } else {
#pragma unroll
            for (int nt = 0; nt < 8; nt++) {
                if (item0 < B) *(float2*)(o0 + 8 * nt) = make_float2(acc[nt][0], acc[nt][1]);
                if (item1 < B) *(float2*)(o1 + 8 * nt) = make_float2(acc[nt][2], acc[nt][3]);
            }
        }
    }
}

extern "C" void kernel_launch(void* const* d_in, const int* in_sizes, int n_in,
                              void* d_out, int out_size)
{
    const int*   seqs   = (const int*)  d_in[0];
    const int*   query  = (const int*)  d_in[1];
    const float* embedW = (const float*)d_in[2];
    const float* W1     = (const float*)d_in[3];
    const float* b1     = (const float*)d_in[4];
    const float* W2     = (const float*)d_in[5];
    const float* b2     = (const float*)d_in[6];
    float*       out    = (float*)d_out;

    const int B = in_sizes[0] / SLEN;

    precompute_kernel<<<512, 256>>>(embedW, W1, b1, W2);

    cudaFuncSetAttribute(lru_main, cudaFuncAttributeMaxDynamicSharedMemorySize, SMEM_TOTAL);
    const int grid = (B + ITEMS - 1) / ITEMS;
    lru_main<<<grid, THREADS, SMEM_TOTAL>>>(seqs, query, b2, out, B);
}